// round 3
// baseline (speedup 1.0000x reference)
#include <cuda_runtime.h>
#include <cuda_bf16.h>
#include <stdint.h>

#define BATCH 8192
#define NIN   1024
#define NOUT  1024
#define KE    1056   // 1024 gelu + 9 seg_x + 9 seg_cnt + 14 zero pad
#define PAD   40     // smem row stride (elements) -> conflict-free frag loads

// ---------------- scratch (module-load allocated, no cudaMalloc) ----------------
__device__ __align__(16) __nv_bfloat16 g_ah[(size_t)BATCH * KE];
__device__ __align__(16) __nv_bfloat16 g_al[(size_t)BATCH * KE];
__device__ __align__(16) __nv_bfloat16 g_bh[(size_t)NOUT * KE];
__device__ __align__(16) __nv_bfloat16 g_bl[(size_t)NOUT * KE];
__device__ __align__(16) float         g_y [(size_t)BATCH * NOUT];

__device__ __forceinline__ void split_bf16(float v, __nv_bfloat16& h, __nv_bfloat16& l) {
    h = __float2bfloat16(v);
    l = __float2bfloat16(v - __bfloat162float(h));
}

__device__ __forceinline__ uint32_t pack2(__nv_bfloat16 a, __nv_bfloat16 b) {
    __nv_bfloat162 t = __halves2bfloat162(a, b);
    return *reinterpret_cast<uint32_t*>(&t);
}

// ---------------- K0: W-side prep: split weights + [slopes0|icpt0] tail ----------------
__global__ void k_wprep(const float* __restrict__ W,
                        const float* __restrict__ slopes,
                        const float* __restrict__ icpts) {
    const int n = blockIdx.x, t = threadIdx.x;
    float4 w = reinterpret_cast<const float4*>(W + (size_t)n * NIN)[t];
    __nv_bfloat16* bh = g_bh + (size_t)n * KE;
    __nv_bfloat16* bl = g_bl + (size_t)n * KE;

    float vv[4] = {w.x, w.y, w.z, w.w};
    __nv_bfloat16 hs[4], ls[4];
#pragma unroll
    for (int e = 0; e < 4; ++e) split_bf16(vv[e], hs[e], ls[e]);

    uint2 uh, ul;
    uh.x = pack2(hs[0], hs[1]); uh.y = pack2(hs[2], hs[3]);
    ul.x = pack2(ls[0], ls[1]); ul.y = pack2(ls[2], ls[3]);
    *reinterpret_cast<uint2*>(bh + t * 4) = uh;
    *reinterpret_cast<uint2*>(bl + t * 4) = ul;

    if (t < 32) {
        float val = 0.0f;
        if (t < 9)       val = slopes[(size_t)n * (NIN * 9) + t];        // slopes[n,0,t]
        else if (t < 18) val = icpts [(size_t)n * (NIN * 9) + (t - 9)];  // intercepts[n,0,t-9]
        __nv_bfloat16 h, l; split_bf16(val, h, l);
        bh[1024 + t] = h;
        bl[1024 + t] = l;
    }
}

// ---------------- K1: x-side prep: gelu split + segment sums/counts tail ----------------
__global__ void k_xprep(const float* __restrict__ x) {
    const int b = blockIdx.x, t = threadIdx.x;
    const int lane = t & 31, wid = t >> 5;

    float4 v4 = reinterpret_cast<const float4*>(x + (size_t)b * NIN)[t];
    float vv[4] = {v4.x, v4.y, v4.z, v4.w};

    // interior grid points g_1..g_8 of linspace(-1,1,10); exact f32 mul+add (no fma)
    float gv[8];
#pragma unroll
    for (int j = 1; j <= 8; ++j)
        gv[j - 1] = __fadd_rn(__fmul_rn((float)j, 2.0f / 9.0f), -1.0f);

    // monotone threshold sums: U[j] = sum x*(x>=g_{j+1}), N[j] = count(x>=g_{j+1}), S = sum x
    float U[8] = {0,0,0,0,0,0,0,0};
    int   N[8] = {0,0,0,0,0,0,0,0};
    float S = 0.0f;

    __nv_bfloat16 hs[4], ls[4];
#pragma unroll
    for (int e = 0; e < 4; ++e) {
        float v = vv[e];
        S += v;
#pragma unroll
        for (int j = 0; j < 8; ++j) {
            bool p = (v >= gv[j]);
            U[j] += p ? v : 0.0f;
            N[j] += p;
        }
        float gl = 0.5f * v * (1.0f + erff(v * 0.70710678118654752f)); // exact gelu
        split_bf16(gl, hs[e], ls[e]);
    }

    __nv_bfloat16* ah = g_ah + (size_t)b * KE;
    __nv_bfloat16* al = g_al + (size_t)b * KE;
    uint2 uh, ul;
    uh.x = pack2(hs[0], hs[1]); uh.y = pack2(hs[2], hs[3]);
    ul.x = pack2(ls[0], ls[1]); ul.y = pack2(ls[2], ls[3]);
    *reinterpret_cast<uint2*>(ah + t * 4) = uh;
    *reinterpret_cast<uint2*>(al + t * 4) = ul;

    // warp tree-reduce (deterministic)
#pragma unroll
    for (int off = 16; off; off >>= 1) {
        S += __shfl_down_sync(0xffffffffu, S, off);
#pragma unroll
        for (int j = 0; j < 8; ++j) {
            U[j] += __shfl_down_sync(0xffffffffu, U[j], off);
            N[j] += __shfl_down_sync(0xffffffffu, N[j], off);
        }
    }

    __shared__ float sU[8][8];
    __shared__ int   sN[8][8];
    __shared__ float sS[8];
    __shared__ float fU[9];   // fU[0..7] = U totals, fU[8] = S total
    __shared__ int   fN[8];

    if (lane == 0) {
        sS[wid] = S;
#pragma unroll
        for (int j = 0; j < 8; ++j) { sU[wid][j] = U[j]; sN[wid][j] = N[j]; }
    }
    __syncthreads();
    if (t < 8) {
        float a = 0.0f; int c = 0;
#pragma unroll
        for (int w = 0; w < 8; ++w) { a += sU[w][t]; c += sN[w][t]; }
        fU[t] = a; fN[t] = c;
    }
    if (t == 8) {
        float a = 0.0f;
#pragma unroll
        for (int w = 0; w < 8; ++w) a += sS[w];
        fU[8] = a;
    }
    __syncthreads();

    if (t < 32) {
        float val = 0.0f;
        if (t < 9) {                       // seg_x[s]
            int s = t;
            val = (s == 0) ? (fU[8] - fU[0]) : (s < 8 ? (fU[s - 1] - fU[s]) : fU[7]);
        } else if (t < 18) {               // seg_cnt[s]
            int s = t - 9;
            int c = (s == 0) ? (NIN - fN[0]) : (s < 8 ? (fN[s - 1] - fN[s]) : fN[7]);
            val = (float)c;
        }
        __nv_bfloat16 h, l; split_bf16(val, h, l);
        ah[1024 + t] = h;
        al[1024 + t] = l;
    }
}

// ---------------- K2: 128x128 tile GEMM, bf16 3-term compensated, mma.sync ----------------
#define MMA_BF16(ACC, A, B)                                                          \
    asm volatile("mma.sync.aligned.m16n8k16.row.col.f32.bf16.bf16.f32 "              \
                 "{%0,%1,%2,%3}, {%4,%5,%6,%7}, {%8,%9}, {%0,%1,%2,%3};\n"           \
                 : "+f"((ACC)[0]), "+f"((ACC)[1]), "+f"((ACC)[2]), "+f"((ACC)[3])    \
                 : "r"((A)[0]), "r"((A)[1]), "r"((A)[2]), "r"((A)[3]),               \
                   "r"((B)[0]), "r"((B)[1]))

__device__ __forceinline__ void load_pre(uint4 pre[8], int Mbase, int Nbase, int k0, int t) {
#pragma unroll
    for (int it = 0; it < 2; ++it) {
        int idx = t + it * 256;
        int m = idx >> 2, sg = idx & 3;
        size_t oA = (size_t)(Mbase + m) * KE + k0 + sg * 8;
        size_t oB = (size_t)(Nbase + m) * KE + k0 + sg * 8;
        pre[it * 4 + 0] = *reinterpret_cast<const uint4*>(g_ah + oA);
        pre[it * 4 + 1] = *reinterpret_cast<const uint4*>(g_al + oA);
        pre[it * 4 + 2] = *reinterpret_cast<const uint4*>(g_bh + oB);
        pre[it * 4 + 3] = *reinterpret_cast<const uint4*>(g_bl + oB);
    }
}

__global__ __launch_bounds__(256, 1) void k_gemm(const float* __restrict__ biases) {
    __shared__ __align__(16) __nv_bfloat16 sAh[128 * PAD];
    __shared__ __align__(16) __nv_bfloat16 sAl[128 * PAD];
    __shared__ __align__(16) __nv_bfloat16 sBh[128 * PAD];
    __shared__ __align__(16) __nv_bfloat16 sBl[128 * PAD];

    const int t = threadIdx.x;
    const int lane = t & 31, wid = t >> 5;
    const int wm = wid & 1, wn = wid >> 1;           // warp 64x32 tile
    const int Mbase = blockIdx.y * 128, Nbase = blockIdx.x * 128;

    float acc[4][4][4];
#pragma unroll
    for (int i = 0; i < 4; ++i)
#pragma unroll
        for (int j = 0; j < 4; ++j)
#pragma unroll
            for (int k = 0; k < 4; ++k) acc[i][j][k] = 0.0f;

    uint4 pre[8];
    load_pre(pre, Mbase, Nbase, 0, t);

    const int r  = lane >> 2;
    const int cq = (lane & 3) << 1;

    for (int kc = 0; kc < KE / 32; ++kc) {
        __syncthreads();   // previous compute done reading smem
        // store prefetched chunk to smem (4B stores: PAD*2 bytes is only 4B-aligned)
#pragma unroll
        for (int it = 0; it < 2; ++it) {
            int idx = t + it * 256;
            int m = idx >> 2, sg = idx & 3;
            int so = m * PAD + sg * 8;
            uint32_t* dAh = reinterpret_cast<uint32_t*>(sAh + so);
            uint32_t* dAl = reinterpret_cast<uint32_t*>(sAl + so);
            uint32_t* dBh = reinterpret_cast<uint32_t*>(sBh + so);
            uint32_t* dBl = reinterpret_cast<uint32_t*>(sBl + so);
            uint4 a = pre[it * 4 + 0]; dAh[0] = a.x; dAh[1] = a.y; dAh[2] = a.z; dAh[3] = a.w;
            uint4 b = pre[it * 4 + 1]; dAl[0] = b.x; dAl[1] = b.y; dAl[2] = b.z; dAl[3] = b.w;
            uint4 c = pre[it * 4 + 2]; dBh[0] = c.x; dBh[1] = c.y; dBh[2] = c.z; dBh[3] = c.w;
            uint4 d = pre[it * 4 + 3]; dBl[0] = d.x; dBl[1] = d.y; dBl[2] = d.z; dBl[3] = d.w;
        }
        __syncthreads();
        if (kc + 1 < KE / 32) load_pre(pre, Mbase, Nbase, (kc + 1) * 32, t); // overlap w/ compute

#pragma unroll
        for (int kk = 0; kk < 32; kk += 16) {
            uint32_t ah[4][4], al4[4][4], bh[4][2], bl[4][2];
#pragma unroll
            for (int mt = 0; mt < 4; ++mt) {
                int row = wm * 64 + mt * 16 + r;
                const __nv_bfloat16* ph = sAh + row * PAD + kk + cq;
                const __nv_bfloat16* pl = sAl + row * PAD + kk + cq;
                ah[mt][0]  = *reinterpret_cast<const uint32_t*>(ph);
                ah[mt][1]  = *reinterpret_cast<const uint32_t*>(ph + 8 * PAD);
                ah[mt][2]  = *reinterpret_cast<const uint32_t*>(ph + 8);
                ah[mt][3]  = *reinterpret_cast<const uint32_t*>(ph + 8 * PAD + 8);
                al4[mt][0] = *reinterpret_cast<const uint32_t*>(pl);
                al4[mt][1] = *reinterpret_cast<const uint32_t*>(pl + 8 * PAD);
                al4[mt][2] = *reinterpret_cast<const uint32_t*>(pl + 8);
                al4[mt][3] = *reinterpret_cast<const uint32_t*>(pl + 8 * PAD + 8);
            }
#pragma unroll
            for (int nt = 0; nt < 4; ++nt) {
                int col = wn * 32 + nt * 8 + r;  // B frag: n = lane>>2, k = (lane&3)*2
                const __nv_bfloat16* ph = sBh + col * PAD + kk + cq;
                const __nv_bfloat16* pl = sBl + col * PAD + kk + cq;
                bh[nt][0] = *reinterpret_cast<const uint32_t*>(ph);
                bh[nt][1] = *reinterpret_cast<const uint32_t*>(ph + 8);
                bl[nt][0] = *reinterpret_cast<const uint32_t*>(pl);
                bl[nt][1] = *reinterpret_cast<const uint32_t*>(pl + 8);
            }
#pragma unroll
            for (int mt = 0; mt < 4; ++mt)
#pragma unroll
                for (int nt = 0; nt < 4; ++nt) {
                    MMA_BF16(acc[mt][nt], ah[mt],  bh[nt]);
                    MMA_BF16(acc[mt][nt], ah[mt],  bl[nt]);
                    MMA_BF16(acc[mt][nt], al4[mt], bh[nt]);
                }
        }
    }

    // epilogue: + bias, store f32 y
#pragma unroll
    for (int nt = 0; nt < 4; ++nt) {
        int col = Nbase + wn * 32 + nt * 8 + cq;
        float2 bia = *reinterpret_cast<const float2*>(biases + col);
#pragma unroll
        for (int mt = 0; mt < 4; ++mt) {
            int row0 = Mbase + wm * 64 + mt * 16 + r;
            float2 v0; v0.x = acc[mt][nt][0] + bia.x; v0.y = acc[mt][nt][1] + bia.y;
            float2 v1; v1.x = acc[mt][nt][2] + bia.x; v1.y = acc[mt][nt][3] + bia.y;
            *reinterpret_cast<float2*>(g_y + (size_t)row0 * NOUT + col)       = v0;
            *reinterpret_cast<float2*>(g_y + (size_t)(row0 + 8) * NOUT + col) = v1;
        }
    }
}

// ---------------- K3: LayerNorm + PReLU ----------------
__global__ void k_ln(float* __restrict__ out, const float* __restrict__ prelu) {
    const int b = blockIdx.x, t = threadIdx.x;
    const int lane = t & 31, wid = t >> 5;

    float4 v = reinterpret_cast<const float4*>(g_y + (size_t)b * NOUT)[t];
    float s = (v.x + v.y) + (v.z + v.w);
    float q = fmaf(v.x, v.x, fmaf(v.y, v.y, fmaf(v.z, v.z, v.w * v.w)));

#pragma unroll
    for (int off = 16; off; off >>= 1) {
        s += __shfl_xor_sync(0xffffffffu, s, off);
        q += __shfl_xor_sync(0xffffffffu, q, off);
    }
    __shared__ float ss[8], sq[8];
    __shared__ float smu, srs;
    if (lane == 0) { ss[wid] = s; sq[wid] = q; }
    __syncthreads();
    if (t == 0) {
        float S = 0.0f, Q = 0.0f;
#pragma unroll
        for (int w = 0; w < 8; ++w) { S += ss[w]; Q += sq[w]; }
        float mu  = S * (1.0f / NOUT);
        float var = Q * (1.0f / NOUT) - mu * mu;
        smu = mu;
        srs = rsqrtf(var + 1e-5f);
    }
    __syncthreads();
    float mu = smu, rs = srs, pw = prelu[0];

    float4 o;
    float yn;
    yn = (v.x - mu) * rs; o.x = (yn >= 0.0f) ? yn : pw * yn;
    yn = (v.y - mu) * rs; o.y = (yn >= 0.0f) ? yn : pw * yn;
    yn = (v.z - mu) * rs; o.z = (yn >= 0.0f) ? yn : pw * yn;
    yn = (v.w - mu) * rs; o.w = (yn >= 0.0f) ? yn : pw * yn;
    reinterpret_cast<float4*>(out + (size_t)b * NOUT)[t] = o;
}

// ---------------- launch ----------------
extern "C" void kernel_launch(void* const* d_in, const int* in_sizes, int n_in,
                              void* d_out, int out_size) {
    const float* x      = (const float*)d_in[0];
    const float* W      = (const float*)d_in[1];
    const float* biases = (const float*)d_in[2];
    const float* slopes = (const float*)d_in[3];
    const float* icpts  = (const float*)d_in[4];
    const float* prelu  = (const float*)d_in[5];
    float* out = (float*)d_out;

    k_wprep<<<NOUT, 256>>>(W, slopes, icpts);
    k_xprep<<<BATCH, 256>>>(x);
    dim3 gg(NOUT / 128, BATCH / 128);
    k_gemm<<<gg, 256>>>(biases);
    k_ln<<<BATCH, 256>>>(out, prelu);
}

// round 5
// speedup vs baseline: 1.0043x; 1.0043x over previous
#include <cuda_runtime.h>
#include <cuda_bf16.h>
#include <stdint.h>

#define BATCH 8192
#define NIN   1024
#define NOUT  1024
#define KE    1152   // 1024 gelu + 9 seg_x + 9 seg_cnt + pad (18 chunks of 64)
#define NCHUNK 18

// smem stage layout (bytes)
#define STR_BH16 144   // bf16 tile row stride (64 bf16 = 128B + 16B pad)
#define STR_A8   80    // A fp8 row stride (64B + 16B pad)
#define STR_B8   72    // B fp8 row stride (64B + 8B pad)
#define OFF_AH   0
#define OFF_BH   36864
#define OFF_A8   55296
#define OFF_AL8  75776
#define OFF_B8   96256
#define OFF_BL8  105472
#define STAGE    114688
#define SMEM_DYN (2 * STAGE)   // 229376 <= 227KB

// ---------------- scratch (module-load allocated, no cudaMalloc) ----------------
__device__ __align__(16) __nv_bfloat16 g_ah[(size_t)BATCH * KE];  // 2048*bf16(gelu)
__device__ __align__(16) uint8_t       g_a8 [(size_t)BATCH * KE]; // e4m3(a)
__device__ __align__(16) uint8_t       g_al8[(size_t)BATCH * KE]; // e4m3((a-ah)*2048)
__device__ __align__(16) __nv_bfloat16 g_bh[(size_t)NOUT * KE];
__device__ __align__(16) uint8_t       g_b8 [(size_t)NOUT * KE];
__device__ __align__(16) uint8_t       g_bl8[(size_t)NOUT * KE];
__device__ __align__(16) float         g_y [(size_t)BATCH * NOUT];

__device__ __forceinline__ uint32_t pack2(__nv_bfloat16 a, __nv_bfloat16 b) {
    __nv_bfloat162 t = __halves2bfloat162(a, b);
    return *reinterpret_cast<uint32_t*>(&t);
}
// cvt d, hi, lo : hi -> high byte, lo -> low byte
__device__ __forceinline__ uint16_t cvt2_e4m3(float hi, float lo) {
    uint16_t r;
    asm("cvt.rn.satfinite.e4m3x2.f32 %0, %1, %2;" : "=h"(r) : "f"(hi), "f"(lo));
    return r;
}
__device__ __forceinline__ uint32_t pack4_e4m3(float v0, float v1, float v2, float v3) {
    return ((uint32_t)cvt2_e4m3(v3, v2) << 16) | (uint32_t)cvt2_e4m3(v1, v0);
}

// ---------------- K0: W-side prep ----------------
__global__ void k_wprep(const float* __restrict__ W,
                        const float* __restrict__ slopes,
                        const float* __restrict__ icpts) {
    const int n = blockIdx.x, t = threadIdx.x;
    float4 w = reinterpret_cast<const float4*>(W + (size_t)n * NIN)[t];
    __nv_bfloat16* bh = g_bh + (size_t)n * KE;
    uint8_t* b8  = g_b8  + (size_t)n * KE;
    uint8_t* bl8 = g_bl8 + (size_t)n * KE;

    float vv[4] = {w.x, w.y, w.z, w.w};
    __nv_bfloat16 hs[4];
    float res[4];
#pragma unroll
    for (int e = 0; e < 4; ++e) {
        hs[e]  = __float2bfloat16(vv[e]);
        res[e] = vv[e] - __bfloat162float(hs[e]);
    }
    uint2 uh;
    uh.x = pack2(hs[0], hs[1]); uh.y = pack2(hs[2], hs[3]);
    *reinterpret_cast<uint2*>(bh + t * 4) = uh;
    *reinterpret_cast<uint32_t*>(b8 + t * 4)  = pack4_e4m3(vv[0], vv[1], vv[2], vv[3]);
    *reinterpret_cast<uint32_t*>(bl8 + t * 4) = pack4_e4m3(res[0] * 2048.0f, res[1] * 2048.0f,
                                                           res[2] * 2048.0f, res[3] * 2048.0f);
    if (t < 128) {   // tail columns 1024..1151 ; b-side fp8 carries extra 2^6
        float val = 0.0f;
        if (t < 9)       val = slopes[(size_t)n * (NIN * 9) + t];
        else if (t < 18) val = icpts [(size_t)n * (NIN * 9) + (t - 9)];
        __nv_bfloat16 h = __float2bfloat16(val);
        float r = val - __bfloat162float(h);
        bh[1024 + t]  = h;
        b8[1024 + t]  = (uint8_t)cvt2_e4m3(0.0f, val * 64.0f);
        bl8[1024 + t] = (uint8_t)cvt2_e4m3(0.0f, r * 2048.0f * 64.0f);
    }
}

// ---------------- K1: x-side prep ----------------
__global__ void k_xprep(const float* __restrict__ x) {
    const int b = blockIdx.x, t = threadIdx.x;
    const int lane = t & 31, wid = t >> 5;

    float4 v4 = reinterpret_cast<const float4*>(x + (size_t)b * NIN)[t];
    float vv[4] = {v4.x, v4.y, v4.z, v4.w};

    float gv[8];
#pragma unroll
    for (int j = 1; j <= 8; ++j)
        gv[j - 1] = __fadd_rn(__fmul_rn((float)j, 2.0f / 9.0f), -1.0f);

    float U[8] = {0,0,0,0,0,0,0,0};
    int   N[8] = {0,0,0,0,0,0,0,0};
    float S = 0.0f;

    float gl[4], res[4];
    __nv_bfloat16 hs[4];
#pragma unroll
    for (int e = 0; e < 4; ++e) {
        float v = vv[e];
        S += v;
#pragma unroll
        for (int j = 0; j < 8; ++j) {
            bool p = (v >= gv[j]);
            U[j] += p ? v : 0.0f;
            N[j] += p;
        }
        gl[e]  = 0.5f * v * (1.0f + erff(v * 0.70710678118654752f));
        hs[e]  = __float2bfloat16(gl[e]);
        res[e] = gl[e] - __bfloat162float(hs[e]);
    }

    __nv_bfloat16* ah = g_ah + (size_t)b * KE;
    uint8_t* a8  = g_a8  + (size_t)b * KE;
    uint8_t* al8 = g_al8 + (size_t)b * KE;
    uint2 uh;
    uh.x = pack2(__float2bfloat16(gl[0] * 2048.0f), __float2bfloat16(gl[1] * 2048.0f));
    uh.y = pack2(__float2bfloat16(gl[2] * 2048.0f), __float2bfloat16(gl[3] * 2048.0f));
    *reinterpret_cast<uint2*>(ah + t * 4) = uh;
    *reinterpret_cast<uint32_t*>(a8 + t * 4)  = pack4_e4m3(gl[0], gl[1], gl[2], gl[3]);
    *reinterpret_cast<uint32_t*>(al8 + t * 4) = pack4_e4m3(res[0] * 2048.0f, res[1] * 2048.0f,
                                                           res[2] * 2048.0f, res[3] * 2048.0f);

#pragma unroll
    for (int j = 0; j < 8; ++j) N[j] = __reduce_add_sync(0xffffffffu, N[j]);
#pragma unroll
    for (int off = 16; off; off >>= 1) {
        S += __shfl_down_sync(0xffffffffu, S, off);
#pragma unroll
        for (int j = 0; j < 8; ++j)
            U[j] += __shfl_down_sync(0xffffffffu, U[j], off);
    }

    __shared__ float sU[8][8];
    __shared__ int   sN[8][8];
    __shared__ float sS[8];
    __shared__ float fU[9];
    __shared__ int   fN[8];

    if (lane == 0) {
        sS[wid] = S;
#pragma unroll
        for (int j = 0; j < 8; ++j) { sU[wid][j] = U[j]; sN[wid][j] = N[j]; }
    }
    __syncthreads();
    if (t < 8) {
        float a = 0.0f; int c = 0;
#pragma unroll
        for (int w = 0; w < 8; ++w) { a += sU[w][t]; c += sN[w][t]; }
        fU[t] = a; fN[t] = c;
    }
    if (t == 8) {
        float a = 0.0f;
#pragma unroll
        for (int w = 0; w < 8; ++w) a += sS[w];
        fU[8] = a;
    }
    __syncthreads();

    if (t < 128) {   // tail columns; a-side fp8 carries extra 2^-6
        float val = 0.0f;
        if (t < 9) {
            int s = t;
            val = (s == 0) ? (fU[8] - fU[0]) : (s < 8 ? (fU[s - 1] - fU[s]) : fU[7]);
        } else if (t < 18) {
            int s = t - 9;
            int c = (s == 0) ? (NIN - fN[0]) : (s < 8 ? (fN[s - 1] - fN[s]) : fN[7]);
            val = (float)c;
        }
        __nv_bfloat16 h = __float2bfloat16(val);
        float r = val - __bfloat162float(h);
        ah[1024 + t]  = __float2bfloat16(val * 2048.0f);
        a8[1024 + t]  = (uint8_t)cvt2_e4m3(0.0f, val * (1.0f / 64.0f));
        al8[1024 + t] = (uint8_t)cvt2_e4m3(0.0f, r * 32.0f);
    }
}

// ---------------- K2: GEMM: bf16 hi-hi + fp8 corrections, cp.async 2-stage ----------------
#define MMA_BF16(ACC, A, B)                                                          \
    asm volatile("mma.sync.aligned.m16n8k16.row.col.f32.bf16.bf16.f32 "              \
                 "{%0,%1,%2,%3}, {%4,%5,%6,%7}, {%8,%9}, {%0,%1,%2,%3};\n"           \
                 : "+f"((ACC)[0]), "+f"((ACC)[1]), "+f"((ACC)[2]), "+f"((ACC)[3])    \
                 : "r"((A)[0]), "r"((A)[1]), "r"((A)[2]), "r"((A)[3]),               \
                   "r"((B)[0]), "r"((B)[1]))

#define MMA_FP8(ACC, A, B)                                                           \
    asm volatile("mma.sync.aligned.m16n8k32.row.col.f32.e4m3.e4m3.f32 "              \
                 "{%0,%1,%2,%3}, {%4,%5,%6,%7}, {%8,%9}, {%0,%1,%2,%3};\n"           \
                 : "+f"((ACC)[0]), "+f"((ACC)[1]), "+f"((ACC)[2]), "+f"((ACC)[3])    \
                 : "r"((A)[0]), "r"((A)[1]), "r"((A)[2]), "r"((A)[3]),               \
                   "r"((B)[0]), "r"((B)[1]))

__device__ __forceinline__ uint32_t smem_u32(const void* p) {
    uint32_t a;
    asm("{ .reg .u64 t; cvta.to.shared.u64 t, %1; cvt.u32.u64 %0, t; }" : "=r"(a) : "l"(p));
    return a;
}
__device__ __forceinline__ void cp16(uint32_t d, const void* s) {
    asm volatile("cp.async.cg.shared.global [%0], [%1], 16;" :: "r"(d), "l"(s));
}
__device__ __forceinline__ void cp8(uint32_t d, const void* s) {
    asm volatile("cp.async.ca.shared.global [%0], [%1], 8;" :: "r"(d), "l"(s));
}

__device__ __forceinline__ void fill_stage(uint32_t sb, int Mbase, int Nbase, int c, int t) {
    const int c64 = c * 64;
#pragma unroll
    for (int j = 0; j < 8; ++j) {            // Ah: 256 rows x 128B
        int id = t + 256 * j, row = id >> 3, seg = id & 7;
        cp16(sb + OFF_AH + row * STR_BH16 + seg * 16,
             g_ah + (size_t)(Mbase + row) * KE + c64 + seg * 8);
    }
#pragma unroll
    for (int j = 0; j < 4; ++j) {            // Bh: 128 rows x 128B
        int id = t + 256 * j, row = id >> 3, seg = id & 7;
        cp16(sb + OFF_BH + row * STR_BH16 + seg * 16,
             g_bh + (size_t)(Nbase + row) * KE + c64 + seg * 8);
    }
#pragma unroll
    for (int j = 0; j < 4; ++j) {            // A8: 256 rows x 64B
        int id = t + 256 * j, row = id >> 2, seg = id & 3;
        cp16(sb + OFF_A8 + row * STR_A8 + seg * 16,
             g_a8 + (size_t)(Mbase + row) * KE + c64 + seg * 16);
    }
#pragma unroll
    for (int j = 0; j < 4; ++j) {            // Al8
        int id = t + 256 * j, row = id >> 2, seg = id & 3;
        cp16(sb + OFF_AL8 + row * STR_A8 + seg * 16,
             g_al8 + (size_t)(Mbase + row) * KE + c64 + seg * 16);
    }
#pragma unroll
    for (int j = 0; j < 4; ++j) {            // B8: 128 rows x 64B (8B chunks, 72B stride)
        int id = t + 256 * j, row = id >> 3, seg = id & 7;
        cp8(sb + OFF_B8 + row * STR_B8 + seg * 8,
            g_b8 + (size_t)(Nbase + row) * KE + c64 + seg * 8);
    }
#pragma unroll
    for (int j = 0; j < 4; ++j) {            // Bl8
        int id = t + 256 * j, row = id >> 3, seg = id & 7;
        cp8(sb + OFF_BL8 + row * STR_B8 + seg * 8,
            g_bl8 + (size_t)(Nbase + row) * KE + c64 + seg * 8);
    }
}

__global__ __launch_bounds__(256, 1) void k_gemm(const float* __restrict__ biases) {
    extern __shared__ char dsm[];
    const uint32_t sbu = smem_u32(dsm);
    const int t = threadIdx.x, lane = t & 31, wid = t >> 5;
    const int wm = wid & 3, wn = wid >> 2;              // warp tile 64x64
    const int Mbase = blockIdx.y * 256, Nbase = blockIdx.x * 128;
    const int r = lane >> 2, cq2 = (lane & 3) * 2, c4 = (lane & 3) * 4;

    float acc[4][8][4];
#pragma unroll
    for (int i = 0; i < 4; ++i)
#pragma unroll
        for (int j = 0; j < 8; ++j)
#pragma unroll
            for (int k = 0; k < 4; ++k) acc[i][j][k] = 0.0f;

    fill_stage(sbu, Mbase, Nbase, 0, t);
    asm volatile("cp.async.commit_group;" ::: "memory");
    fill_stage(sbu + STAGE, Mbase, Nbase, 1, t);
    asm volatile("cp.async.commit_group;" ::: "memory");

    for (int c = 0; c < NCHUNK; ++c) {
        const char* st = dsm + (c & 1) * STAGE;
        const __nv_bfloat16* sAh = (const __nv_bfloat16*)(st + OFF_AH);
        const __nv_bfloat16* sBh = (const __nv_bfloat16*)(st + OFF_BH);
        const char* sA8  = st + OFF_A8;
        const char* sAl8 = st + OFF_AL8;
        const char* sB8  = st + OFF_B8;
        const char* sBl8 = st + OFF_BL8;

        asm volatile("cp.async.wait_group 1;" ::: "memory");
        __syncthreads();

        // ---- bf16 hi-hi ----
#pragma unroll
        for (int kh = 0; kh < 4; ++kh) {
            uint32_t af[4][4], bf_[8][2];
#pragma unroll
            for (int mt = 0; mt < 4; ++mt) {
                int base = (wm * 64 + mt * 16 + r) * 72 + kh * 16 + cq2;  // elt units
                af[mt][0] = *(const uint32_t*)(sAh + base);
                af[mt][1] = *(const uint32_t*)(sAh + base + 8 * 72);
                af[mt][2] = *(const uint32_t*)(sAh + base + 8);
                af[mt][3] = *(const uint32_t*)(sAh + base + 8 * 72 + 8);
            }
#pragma unroll
            for (int nt = 0; nt < 8; ++nt) {
                int nb = (wn * 64 + nt * 8 + r) * 72 + kh * 16 + cq2;
                bf_[nt][0] = *(const uint32_t*)(sBh + nb);
                bf_[nt][1] = *(const uint32_t*)(sBh + nb + 8);
            }
#pragma unroll
            for (int mt = 0; mt < 4; ++mt)
#pragma unroll
                for (int nt = 0; nt < 8; ++nt)
                    MMA_BF16(acc[mt][nt], af[mt], bf_[nt]);
        }

        // ---- fp8 corrections: a8*bl8 + al8*b8 ----
#pragma unroll
        for (int kq = 0; kq < 2; ++kq) {
            {   // term1
                uint32_t af[4][4], bf_[8][2];
#pragma unroll
                for (int mt = 0; mt < 4; ++mt) {
                    int base = (wm * 64 + mt * 16 + r) * STR_A8 + kq * 32 + c4;
                    af[mt][0] = *(const uint32_t*)(sA8 + base);
                    af[mt][1] = *(const uint32_t*)(sA8 + base + 8 * STR_A8);
                    af[mt][2] = *(const uint32_t*)(sA8 + base + 16);
                    af[mt][3] = *(const uint32_t*)(sA8 + base + 8 * STR_A8 + 16);
                }
#pragma unroll
                for (int nt = 0; nt < 8; ++nt) {
                    int nb = (wn * 64 + nt * 8 + r) * STR_B8 + kq * 32 + c4;
                    bf_[nt][0] = *(const uint32_t*)(sBl8 + nb);
                    bf_[nt][1] = *(const uint32_t*)(sBl8 + nb + 16);
                }
#pragma unroll
                for (int mt = 0; mt < 4; ++mt)
#pragma unroll
                    for (int nt = 0; nt < 8; ++nt)
                        MMA_FP8(acc[mt][nt], af[mt], bf_[nt]);
            }
            {   // term2
                uint32_t af[4][4], bf_[8][2];
#pragma unroll
                for (int mt = 0; mt < 4; ++mt) {
                    int base = (wm * 64 + mt * 16 + r) * STR_A8 + kq * 32 + c4;
                    af[mt][0] = *(const uint32_t*)(sAl8 + base);
                    af[mt][1] = *(const uint32_t*)(sAl8 + base + 8 * STR_A8);
                    af[mt][2] = *(const uint32_t*)(sAl8 + base + 16);
                    af[mt][3] = *(const uint32_t*)(sAl8 + base + 8 * STR_A8 + 16);
                }
#pragma unroll
                for (int nt = 0; nt < 8; ++nt) {
                    int nb = (wn * 64 + nt * 8 + r) * STR_B8 + kq * 32 + c4;
                    bf_[nt][0] = *(const uint32_t*)(sB8 + nb);
                    bf_[nt][1] = *(const uint32_t*)(sB8 + nb + 16);
                }
#pragma unroll
                for (int mt = 0; mt < 4; ++mt)
#pragma unroll
                    for (int nt = 0; nt < 8; ++nt)
                        MMA_FP8(acc[mt][nt], af[mt], bf_[nt]);
            }
        }

        __syncthreads();
        if (c + 2 < NCHUNK)
            fill_stage(sbu + (c & 1) * STAGE, Mbase, Nbase, c + 2, t);
        asm volatile("cp.async.commit_group;" ::: "memory");
    }

    // epilogue: y = acc * 2^-11 + bias  (32B-sector-aligned float2 stores)
    const float INV = 1.0f / 2048.0f;
#pragma unroll
    for (int nt = 0; nt < 8; ++nt) {
        int col = Nbase + wn * 64 + nt * 8 + cq2;
        float2 bia = *reinterpret_cast<const float2*>(biases + col);
#pragma unroll
        for (int mt = 0; mt < 4; ++mt) {
            int row0 = Mbase + wm * 64 + mt * 16 + r;
            float2 v0, v1;
            v0.x = fmaf(acc[mt][nt][0], INV, bia.x);
            v0.y = fmaf(acc[mt][nt][1], INV, bia.y);
            v1.x = fmaf(acc[mt][nt][2], INV, bia.x);
            v1.y = fmaf(acc[mt][nt][3], INV, bia.y);
            *reinterpret_cast<float2*>(g_y + (size_t)row0 * NOUT + col)       = v0;
            *reinterpret_cast<float2*>(g_y + (size_t)(row0 + 8) * NOUT + col) = v1;
        }
    }
}

// ---------------- K3: LayerNorm + PReLU ----------------
__global__ void k_ln(float* __restrict__ out, const float* __restrict__ prelu) {
    const int b = blockIdx.x, t = threadIdx.x;
    const int lane = t & 31, wid = t >> 5;

    float4 v = reinterpret_cast<const float4*>(g_y + (size_t)b * NOUT)[t];
    float s = (v.x + v.y) + (v.z + v.w);
    float q = fmaf(v.x, v.x, fmaf(v.y, v.y, fmaf(v.z, v.z, v.w * v.w)));

#pragma unroll
    for (int off = 16; off; off >>= 1) {
        s += __shfl_xor_sync(0xffffffffu, s, off);
        q += __shfl_xor_sync(0xffffffffu, q, off);
    }
    __shared__ float ss[8], sq[8];
    __shared__ float smu, srs;
    if (lane == 0) { ss[wid] = s; sq[wid] = q; }
    __syncthreads();
    if (t == 0) {
        float S = 0.0f, Q = 0.0f;
#pragma unroll
        for (int w = 0; w < 8; ++w) { S += ss[w]; Q += sq[w]; }
        float mu  = S * (1.0f / NOUT);
        float var = Q * (1.0f / NOUT) - mu * mu;
        smu = mu;
        srs = rsqrtf(var + 1e-5f);
    }
    __syncthreads();
    float mu = smu, rs = srs, pw = prelu[0];

    float4 o;
    float yn;
    yn = (v.x - mu) * rs; o.x = (yn >= 0.0f) ? yn : pw * yn;
    yn = (v.y - mu) * rs; o.y = (yn >= 0.0f) ? yn : pw * yn;
    yn = (v.z - mu) * rs; o.z = (yn >= 0.0f) ? yn : pw * yn;
    yn = (v.w - mu) * rs; o.w = (yn >= 0.0f) ? yn : pw * yn;
    reinterpret_cast<float4*>(out + (size_t)b * NOUT)[t] = o;
}

// ---------------- launch ----------------
extern "C" void kernel_launch(void* const* d_in, const int* in_sizes, int n_in,
                              void* d_out, int out_size) {
    const float* x      = (const float*)d_in[0];
    const float* W      = (const float*)d_in[1];
    const float* biases = (const float*)d_in[2];
    const float* slopes = (const float*)d_in[3];
    const float* icpts  = (const float*)d_in[4];
    const float* prelu  = (const float*)d_in[5];
    float* out = (float*)d_out;

    static bool attr_set = false;
    if (!attr_set) {
        cudaFuncSetAttribute(k_gemm, cudaFuncAttributeMaxDynamicSharedMemorySize, SMEM_DYN);
        attr_set = true;
    }

    k_wprep<<<NOUT, 256>>>(W, slopes, icpts);
    k_xprep<<<BATCH, 256>>>(x);
    dim3 gg(NOUT / 128, BATCH / 256);
    k_gemm<<<gg, 256, SMEM_DYN>>>(biases);
    k_ln<<<BATCH, 256>>>(out, prelu);
}

// round 6
// speedup vs baseline: 2.4001x; 2.3899x over previous
#include <cuda_runtime.h>
#include <cuda_fp16.h>
#include <stdint.h>

#define BATCH 8192
#define NIN   1024
#define NOUT  1024
#define KE    1088   // 1024 gelu + 45 tail (seg_x/slope + cnt/icpt splits) + pad
#define NCHUNK 17    // K-chunks of 64
#define STR    144   // smem row stride bytes (64 fp16 = 128B + 16B pad)
#define STRH   72    // stride in half units
#define OFF_B  36864 // A: 256 rows * 144B
#define STAGE  55296 // A (36864) + B (18432)
#define STAGES 4
#define SMEM_DYN (STAGES * STAGE)  // 221184

// ---------------- scratch (module-load allocated, no cudaMalloc) ----------------
__device__ __align__(16) __half g_a[(size_t)BATCH * KE];
__device__ __align__(16) __half g_b[(size_t)NOUT * KE];
__device__ __align__(16) float  g_y[(size_t)BATCH * NOUT];

__device__ __forceinline__ uint32_t packh2(__half a, __half b) {
    __half2 t = __halves2half2(a, b);
    return *reinterpret_cast<uint32_t*>(&t);
}

// ---------------- K0: W-side prep: fp16(W) + tail coeff columns ----------------
__global__ void k_wprep(const float* __restrict__ W,
                        const float* __restrict__ slopes,
                        const float* __restrict__ icpts) {
    const int n = blockIdx.x, t = threadIdx.x;
    float4 w = reinterpret_cast<const float4*>(W + (size_t)n * NIN)[t];
    __half* b = g_b + (size_t)n * KE;

    uint2 u;
    u.x = packh2(__float2half(w.x), __float2half(w.y));
    u.y = packh2(__float2half(w.z), __float2half(w.w));
    *reinterpret_cast<uint2*>(b + t * 4) = u;

    if (t < 64) {   // tail cols 1024..1087
        float val = 0.0f;
        if (t < 45) {
            int s = t / 5, r = t % 5;
            float p = slopes[(size_t)n * (NIN * 9) + s];   // slopes[n,0,s]
            float q = icpts [(size_t)n * (NIN * 9) + s];   // intercepts[n,0,s]
            __half ph = __float2half(p);
            __half qh = __float2half(q);
            if      (r == 0) val = __half2float(ph);                 // pairs sh
            else if (r == 1) val = p - __half2float(ph);             // pl, pairs sh
            else if (r == 2) val = __half2float(ph);                 // pairs sl
            else if (r == 3) val = __half2float(qh);                 // pairs cnt
            else             val = q - __half2float(qh);             // ql, pairs cnt
        }
        b[1024 + t] = __float2half(val);
    }
}

// ---------------- K1: x-side prep: fp16(gelu) + segment feature tail ----------------
__global__ void k_xprep(const float* __restrict__ x) {
    const int b = blockIdx.x, t = threadIdx.x;
    const int lane = t & 31, wid = t >> 5;

    float4 v4 = reinterpret_cast<const float4*>(x + (size_t)b * NIN)[t];
    float vv[4] = {v4.x, v4.y, v4.z, v4.w};

    float gv[8];
#pragma unroll
    for (int j = 1; j <= 8; ++j)
        gv[j - 1] = __fadd_rn(__fmul_rn((float)j, 2.0f / 9.0f), -1.0f);

    float U[8] = {0,0,0,0,0,0,0,0};
    int   N[8] = {0,0,0,0,0,0,0,0};
    float S = 0.0f;
    float gl[4];
#pragma unroll
    for (int e = 0; e < 4; ++e) {
        float v = vv[e];
        S += v;
#pragma unroll
        for (int j = 0; j < 8; ++j) {
            bool p = (v >= gv[j]);
            U[j] += p ? v : 0.0f;
            N[j] += p;
        }
        gl[e] = 0.5f * v * (1.0f + erff(v * 0.70710678118654752f));
    }

    __half* a = g_a + (size_t)b * KE;
    uint2 u;
    u.x = packh2(__float2half(gl[0]), __float2half(gl[1]));
    u.y = packh2(__float2half(gl[2]), __float2half(gl[3]));
    *reinterpret_cast<uint2*>(a + t * 4) = u;

#pragma unroll
    for (int j = 0; j < 8; ++j) N[j] = __reduce_add_sync(0xffffffffu, N[j]);
#pragma unroll
    for (int off = 16; off; off >>= 1) {
        S += __shfl_down_sync(0xffffffffu, S, off);
#pragma unroll
        for (int j = 0; j < 8; ++j)
            U[j] += __shfl_down_sync(0xffffffffu, U[j], off);
    }

    __shared__ float sU[8][8];
    __shared__ int   sN[8][8];
    __shared__ float sS[8];
    __shared__ float fU[9];
    __shared__ int   fN[8];

    if (lane == 0) {
        sS[wid] = S;
#pragma unroll
        for (int j = 0; j < 8; ++j) { sU[wid][j] = U[j]; sN[wid][j] = N[j]; }
    }
    __syncthreads();
    if (t < 8) {
        float acc = 0.0f; int c = 0;
#pragma unroll
        for (int w = 0; w < 8; ++w) { acc += sU[w][t]; c += sN[w][t]; }
        fU[t] = acc; fN[t] = c;
    }
    if (t == 8) {
        float acc = 0.0f;
#pragma unroll
        for (int w = 0; w < 8; ++w) acc += sS[w];
        fU[8] = acc;
    }
    __syncthreads();

    if (t < 64) {   // tail cols 1024..1087
        float val = 0.0f;
        if (t < 45) {
            int s = t / 5, r = t % 5;
            float sx  = (s == 0) ? (fU[8] - fU[0]) : (s < 8 ? (fU[s - 1] - fU[s]) : fU[7]);
            int   cnt = (s == 0) ? (NIN - fN[0])   : (s < 8 ? (fN[s - 1] - fN[s]) : fN[7]);
            __half sh = __float2half(sx);
            if      (r == 0) val = __half2float(sh);         // sh (pairs ph)
            else if (r == 1) val = __half2float(sh);         // sh (pairs pl)
            else if (r == 2) val = sx - __half2float(sh);    // sl (pairs ph)
            else             val = (float)cnt;               // cnt exact (pairs qh, ql)
        }
        a[1024 + t] = __float2half(val);
    }
}

// ---------------- K2: single-term fp16 GEMM, 256x128 tile, 4-stage cp.async ----------------
#define MMA_F16(ACC, A, B)                                                           \
    asm volatile("mma.sync.aligned.m16n8k16.row.col.f32.f16.f16.f32 "                \
                 "{%0,%1,%2,%3}, {%4,%5,%6,%7}, {%8,%9}, {%0,%1,%2,%3};\n"           \
                 : "+f"((ACC)[0]), "+f"((ACC)[1]), "+f"((ACC)[2]), "+f"((ACC)[3])    \
                 : "r"((A)[0]), "r"((A)[1]), "r"((A)[2]), "r"((A)[3]),               \
                   "r"((B)[0]), "r"((B)[1]))

__device__ __forceinline__ uint32_t smem_u32(const void* p) {
    uint32_t a;
    asm("{ .reg .u64 t; cvta.to.shared.u64 t, %1; cvt.u32.u64 %0, t; }" : "=r"(a) : "l"(p));
    return a;
}
__device__ __forceinline__ void cp16(uint32_t d, const void* s) {
    asm volatile("cp.async.cg.shared.global [%0], [%1], 16;" :: "r"(d), "l"(s));
}

__device__ __forceinline__ void fill_stage(uint32_t sb, int Mbase, int Nbase, int c, int t) {
    const int c64 = c * 64;
#pragma unroll
    for (int j = 0; j < 8; ++j) {            // A: 256 rows x 128B
        int id = t + 256 * j, row = id >> 3, seg = id & 7;
        cp16(sb + row * STR + seg * 16,
             g_a + (size_t)(Mbase + row) * KE + c64 + seg * 8);
    }
#pragma unroll
    for (int j = 0; j < 4; ++j) {            // B: 128 rows x 128B
        int id = t + 256 * j, row = id >> 3, seg = id & 7;
        cp16(sb + OFF_B + row * STR + seg * 16,
             g_b + (size_t)(Nbase + row) * KE + c64 + seg * 8);
    }
}

__global__ __launch_bounds__(256, 1) void k_gemm(const float* __restrict__ biases) {
    extern __shared__ char dsm[];
    const uint32_t sbu = smem_u32(dsm);
    const int t = threadIdx.x, lane = t & 31, wid = t >> 5;
    const int wm = wid & 3, wn = wid >> 2;              // warp tile 64x64
    const int Mbase = blockIdx.y * 256, Nbase = blockIdx.x * 128;
    const int r = lane >> 2, cq2 = (lane & 3) * 2;

    float acc[4][8][4];
#pragma unroll
    for (int i = 0; i < 4; ++i)
#pragma unroll
        for (int j = 0; j < 8; ++j)
#pragma unroll
            for (int k = 0; k < 4; ++k) acc[i][j][k] = 0.0f;

    // prologue: fill 3 stages
#pragma unroll
    for (int p = 0; p < 3; ++p) {
        fill_stage(sbu + p * STAGE, Mbase, Nbase, p, t);
        asm volatile("cp.async.commit_group;" ::: "memory");
    }

    for (int c = 0; c < NCHUNK; ++c) {
        const __half* st = (const __half*)(dsm + (c & 3) * STAGE);
        const __half* sB = (const __half*)(dsm + (c & 3) * STAGE + OFF_B);

        asm volatile("cp.async.wait_group 2;" ::: "memory");
        __syncthreads();

#pragma unroll
        for (int kh = 0; kh < 4; ++kh) {
            uint32_t af[4][4], bf_[8][2];
#pragma unroll
            for (int mt = 0; mt < 4; ++mt) {
                int base = (wm * 64 + mt * 16 + r) * STRH + kh * 16 + cq2;
                af[mt][0] = *(const uint32_t*)(st + base);
                af[mt][1] = *(const uint32_t*)(st + base + 8 * STRH);
                af[mt][2] = *(const uint32_t*)(st + base + 8);
                af[mt][3] = *(const uint32_t*)(st + base + 8 * STRH + 8);
            }
#pragma unroll
            for (int nt = 0; nt < 8; ++nt) {
                int nb = (wn * 64 + nt * 8 + r) * STRH + kh * 16 + cq2;
                bf_[nt][0] = *(const uint32_t*)(sB + nb);
                bf_[nt][1] = *(const uint32_t*)(sB + nb + 8);
            }
#pragma unroll
            for (int mt = 0; mt < 4; ++mt)
#pragma unroll
                for (int nt = 0; nt < 8; ++nt)
                    MMA_F16(acc[mt][nt], af[mt], bf_[nt]);
        }

        // prefetch chunk c+3 into stage (c+3)&3 (consumed at c-1; all warps past that sync)
        if (c + 3 < NCHUNK)
            fill_stage(sbu + ((c + 3) & 3) * STAGE, Mbase, Nbase, c + 3, t);
        asm volatile("cp.async.commit_group;" ::: "memory");
    }

    // epilogue: y = acc + bias
#pragma unroll
    for (int nt = 0; nt < 8; ++nt) {
        int col = Nbase + wn * 64 + nt * 8 + cq2;
        float2 bia = *reinterpret_cast<const float2*>(biases + col);
#pragma unroll
        for (int mt = 0; mt < 4; ++mt) {
            int row0 = Mbase + wm * 64 + mt * 16 + r;
            float2 v0, v1;
            v0.x = acc[mt][nt][0] + bia.x;
            v0.y = acc[mt][nt][1] + bia.y;
            v1.x = acc[mt][nt][2] + bia.x;
            v1.y = acc[mt][nt][3] + bia.y;
            *reinterpret_cast<float2*>(g_y + (size_t)row0 * NOUT + col)       = v0;
            *reinterpret_cast<float2*>(g_y + (size_t)(row0 + 8) * NOUT + col) = v1;
        }
    }
}

// ---------------- K3: LayerNorm + PReLU ----------------
__global__ void k_ln(float* __restrict__ out, const float* __restrict__ prelu) {
    const int b = blockIdx.x, t = threadIdx.x;
    const int lane = t & 31, wid = t >> 5;

    float4 v = reinterpret_cast<const float4*>(g_y + (size_t)b * NOUT)[t];
    float s = (v.x + v.y) + (v.z + v.w);
    float q = fmaf(v.x, v.x, fmaf(v.y, v.y, fmaf(v.z, v.z, v.w * v.w)));

#pragma unroll
    for (int off = 16; off; off >>= 1) {
        s += __shfl_xor_sync(0xffffffffu, s, off);
        q += __shfl_xor_sync(0xffffffffu, q, off);
    }
    __shared__ float ss[8], sq[8];
    __shared__ float smu, srs;
    if (lane == 0) { ss[wid] = s; sq[wid] = q; }
    __syncthreads();
    if (t == 0) {
        float S = 0.0f, Q = 0.0f;
#pragma unroll
        for (int w = 0; w < 8; ++w) { S += ss[w]; Q += sq[w]; }
        float mu  = S * (1.0f / NOUT);
        float var = Q * (1.0f / NOUT) - mu * mu;
        smu = mu;
        srs = rsqrtf(var + 1e-5f);
    }
    __syncthreads();
    float mu = smu, rs = srs, pw = prelu[0];

    float4 o;
    float yn;
    yn = (v.x - mu) * rs; o.x = (yn >= 0.0f) ? yn : pw * yn;
    yn = (v.y - mu) * rs; o.y = (yn >= 0.0f) ? yn : pw * yn;
    yn = (v.z - mu) * rs; o.z = (yn >= 0.0f) ? yn : pw * yn;
    yn = (v.w - mu) * rs; o.w = (yn >= 0.0f) ? yn : pw * yn;
    reinterpret_cast<float4*>(out + (size_t)b * NOUT)[t] = o;
}

// ---------------- launch ----------------
extern "C" void kernel_launch(void* const* d_in, const int* in_sizes, int n_in,
                              void* d_out, int out_size) {
    const float* x      = (const float*)d_in[0];
    const float* W      = (const float*)d_in[1];
    const float* biases = (const float*)d_in[2];
    const float* slopes = (const float*)d_in[3];
    const float* icpts  = (const float*)d_in[4];
    const float* prelu  = (const float*)d_in[5];
    float* out = (float*)d_out;

    cudaFuncSetAttribute(k_gemm, cudaFuncAttributeMaxDynamicSharedMemorySize, SMEM_DYN);

    k_wprep<<<NOUT, 256>>>(W, slopes, icpts);
    k_xprep<<<BATCH, 256>>>(x);
    dim3 gg(NOUT / 128, BATCH / 256);
    k_gemm<<<gg, 256, SMEM_DYN>>>(biases);
    k_ln<<<BATCH, 256>>>(out, prelu);
}